// round 16
// baseline (speedup 1.0000x reference)
#include <cuda_runtime.h>
#include <cuda_bf16.h>

// BBAStar: 8-connected grid shortest path, B=128, 32x32.
// R15 = R14 with the pick8d typo fixed (direction (1,0) delta is 32, not 31).
// Structure: R4 alternating V/H band GS hot loop (KP=2, 3-barrier flag
// protocol, fresh shfls) + 3x-compressed serial backtrack: successor indices
// nxt[v] (exact OFFS first-occurrence argmin, source self-loop) composed in
// parallel into packed 3-hop words (n1 | n2<<10 | n3<<20); serial walk does
// one LDS per 3 path cells. Sticky source self-loop => marks past the source
// re-mark the source (idempotent), matching the reference's frozen-pos
// semantics. Relaxation: monotone fl(w + exact-min8) on valid upper bounds
// => bit-exact float fixed point of the reference's 1024 Jacobi sweeps;
// zero-change epoch => fixed point verified.

#define BN 128
#define ST 35              // smem row stride (odd => conflict-free both axes)
#define INF_F 1000000000.0f
#define EPS_F 1e-6f
#define KP 2               // fwd+bwd sweep pairs per phase

__device__ __forceinline__ float shl(float v, int lane) {
    float t = __shfl_up_sync(0xffffffffu, v, 1);
    return (lane == 0) ? INF_F : t;
}
__device__ __forceinline__ float shr(float v, int lane) {
    float t = __shfl_down_sync(0xffffffffu, v, 1);
    return (lane == 31) ? INF_F : t;
}
__device__ __forceinline__ float min8f(float a, float b, float c, float d,
                                       float e, float f, float g, float h) {
    return fminf(fminf(fminf(a, b), fminf(c, d)),
                 fminf(fminf(e, f), fminf(g, h)));
}
// OFFS-order first-occurrence argmin; returns linear delta dr*32+dc.
// OFFS: (-1,-1)->-33, (-1,0)->-32, (-1,1)->-31, (0,-1)->-1, (0,1)->+1,
//       (1,-1)->+31,  (1,0)->+32,  (1,1)->+33
__device__ __forceinline__ int pick8d(float a0, float a1, float a2, float a3,
                                      float a4, float a5, float a6, float a7) {
    float bb = a0; int bd = -33;
    if (a1 < bb) { bb = a1; bd = -32; }
    if (a2 < bb) { bb = a2; bd = -31; }
    if (a3 < bb) { bb = a3; bd = -1; }
    if (a4 < bb) { bb = a4; bd = 1; }
    if (a5 < bb) { bb = a5; bd = 31; }
    if (a6 < bb) { bb = a6; bd = 32; }
    if (a7 < bb) { bb = a7; bd = 33; }
    return bd;
}

// One GS fwd+bwd sweep pair over 4 owned cells per lane (R4 version:
// fresh shfls per row, diagonal-inclusive Gauss-Seidel).
__device__ __forceinline__ void sweep_pair(volatile float* vd,
                                           const float w[4], float d[4],
                                           int i0, int di, int ix, int iy,
                                           int lane, bool& any)
{
    // forward sweep
    {
        float X = vd[ix], Y = vd[iy];
        float p = X, pl = shl(X, lane), pr = shr(X, lane);
        #pragma unroll
        for (int i = 0; i < 4; ++i) {
            float nx = (i < 3) ? d[i + 1] : Y;
            float nl = shl(nx, lane),  nr = shr(nx, lane);
            float cl = shl(d[i], lane), cr = shr(d[i], lane);
            float v = w[i] + min8f(pl, p, pr, cl, cr, nl, nx, nr);
            if (v < d[i]) { d[i] = v; vd[i0 + i * di] = v; any = true; }
            p = d[i]; pl = shl(p, lane); pr = shr(p, lane);
        }
    }
    // backward sweep
    {
        float X = vd[ix], Y = vd[iy];
        float p = Y, pl = shl(Y, lane), pr = shr(Y, lane);
        #pragma unroll
        for (int i = 3; i >= 0; --i) {
            float nx = (i > 0) ? d[i - 1] : X;
            float nl = shl(nx, lane),  nr = shr(nx, lane);
            float cl = shl(d[i], lane), cr = shr(d[i], lane);
            float v = w[i] + min8f(nl, nx, nr, cl, cr, pl, p, pr);
            if (v < d[i]) { d[i] = v; vd[i0 + i * di] = v; any = true; }
            p = d[i]; pl = shl(p, lane); pr = shr(p, lane);
        }
    }
}

__global__ void __launch_bounds__(256, 1)
bba_kernel(const float* __restrict__ weights,
           const int*   __restrict__ source,
           const int*   __restrict__ target,
           float*       __restrict__ out)
{
    __shared__ float dist[34 * ST];     // padded 34x34, stride 35
    __shared__ float wsh[32][33];       // weights, conflict-free both axes
    __shared__ int   nxt[1024];         // 1-hop successor indices
    __shared__ int   pk[1024];          // packed 3-hop words
    __shared__ int   changed;
    volatile float* vd = dist;

    const int b    = blockIdx.x;
    const int tid  = threadIdx.x;
    const int wpid = tid >> 5;          // warp id 0..7
    const int lane = tid & 31;
    const int r0   = 4 * wpid;          // V band first row
    const int c0   = 4 * wpid;          // H band first col

    // Zero poisoned output slice.
    #pragma unroll
    for (int i = 0; i < 4; ++i) out[b * 1024 + i * 256 + tid] = 0.0f;

    for (int i = tid; i < 34 * ST; i += 256) dist[i] = INF_F;

    // Weights (+EPS), V-layout load, stash in smem for H-layout reads.
    const float* wb = weights + b * 1024;
    float wv[4], wh[4];
    #pragma unroll
    for (int i = 0; i < 4; ++i) {
        wv[i] = wb[(r0 + i) * 32 + lane] + EPS_F;
        wsh[r0 + i][lane] = wv[i];
    }

    const int sr = source[2 * b + 0];
    const int sc = source[2 * b + 1];
    const int tr = target[2 * b + 0];
    const int tc = target[2 * b + 1];

    __syncthreads();

    #pragma unroll
    for (int i = 0; i < 4; ++i) wh[i] = wsh[lane][c0 + i];
    if (tid == 0) dist[(sr + 1) * ST + (sc + 1)] = wsh[sr][sc];
    __syncthreads();

    // Indices for both orientations.
    const int v_i0 = (r0 + 1) * ST + (lane + 1);   // own cells, step ST
    const int v_ix = (r0 + 0) * ST + (lane + 1);   // row above band
    const int v_iy = (r0 + 5) * ST + (lane + 1);   // row below band
    const int h_i0 = (lane + 1) * ST + (c0 + 1);   // own cells, step 1
    const int h_ix = (lane + 1) * ST + (c0 + 0);   // col left of band
    const int h_iy = (lane + 1) * ST + (c0 + 5);   // col right of band

    float d[4];

    for (;;) {
        bool any = false;

        // V phase
        #pragma unroll
        for (int i = 0; i < 4; ++i) d[i] = vd[v_i0 + i * ST];
        #pragma unroll 1
        for (int k = 0; k < KP; ++k)
            sweep_pair(vd, wv, d, v_i0, ST, v_ix, v_iy, lane, any);

        __syncthreads();                 // V writes visible to H phase

        // H phase
        #pragma unroll
        for (int i = 0; i < 4; ++i) d[i] = vd[h_i0 + i];
        #pragma unroll 1
        for (int k = 0; k < KP; ++k)
            sweep_pair(vd, wh, d, h_i0, 1, h_ix, h_iy, lane, any);

        if (any) changed = 1;            // benign race
        __syncthreads();
        int c0f = changed;
        __syncthreads();
        if (!c0f) break;                 // zero-change epoch => fixed point
        if (tid == 0) changed = 0;
        __syncthreads();
    }

    const int sidx = (sr << 5) + sc;

    // 1-hop successors (V layout), OFFS order, source = self-loop:
    // (-1,-1),(-1,0),(-1,1),(0,-1),(0,1),(1,-1),(1,0),(1,1)
    {
        #pragma unroll
        for (int i = 0; i < 4; ++i) d[i] = vd[v_i0 + i * ST];
        float X  = vd[v_ix], Y = vd[v_iy];
        float XL = shl(X, lane),    XR = shr(X, lane);
        float L0 = shl(d[0], lane), R0 = shr(d[0], lane);
        float L1 = shl(d[1], lane), R1 = shr(d[1], lane);
        float L2 = shl(d[2], lane), R2 = shr(d[2], lane);
        float L3 = shl(d[3], lane), R3 = shr(d[3], lane);
        float YL = shl(Y, lane),    YR = shr(Y, lane);
        int dl[4];
        dl[0] = pick8d(XL, X,    XR, L0, R0, L1, d[1], R1);
        dl[1] = pick8d(L0, d[0], R0, L1, R1, L2, d[2], R2);
        dl[2] = pick8d(L1, d[1], R1, L2, R2, L3, d[3], R3);
        dl[3] = pick8d(L2, d[2], R2, L3, R3, YL, Y,    YR);
        #pragma unroll
        for (int i = 0; i < 4; ++i) {
            const int cell = ((r0 + i) << 5) + lane;
            nxt[cell] = (cell == sidx) ? sidx : (cell + dl[i]);
        }
    }
    __syncthreads();

    // Compose 3 hops into one packed word per cell (parallel).
    #pragma unroll
    for (int k = 0; k < 4; ++k) {
        const int v  = k * 256 + tid;
        const int n1 = nxt[v];
        const int n2 = nxt[n1];
        const int n3 = nxt[n2];
        pk[v] = n1 | (n2 << 10) | (n3 << 20);
    }
    __syncthreads();

    // Serial walk: one LDS per 3 path cells (sticky at source).
    if (tid == 0) {
        int idx = (tr << 5) + tc;
        float* o = out + b * 1024;
        for (int step = 0; step < 344; ++step) {
            const int w3 = pk[idx];
            o[idx] = 1.0f;
            if (idx == sidx) break;
            o[w3 & 1023] = 1.0f;           // n1 (source-sticky => idempotent)
            o[(w3 >> 10) & 1023] = 1.0f;   // n2
            idx = (w3 >> 20) & 1023;       // jump 3 hops
        }
    }
}

extern "C" void kernel_launch(void* const* d_in, const int* in_sizes, int n_in,
                              void* d_out, int out_size)
{
    const float* weights = (const float*)d_in[0];
    const int*   source  = (const int*)d_in[1];
    const int*   target  = (const int*)d_in[2];
    float*       out     = (float*)d_out;

    bba_kernel<<<BN, 256>>>(weights, source, target, out);
}

// round 17
// speedup vs baseline: 1.0152x; 1.0152x over previous
#include <cuda_runtime.h>
#include <cuda_bf16.h>

// BBAStar: 8-connected grid shortest path, B=128, 32x32.
// R16 = R15 (best-measured: R4 alternating V/H band GS hot loop with fresh
// shfls, KP=2; packed 3-hop backtrack) with ONE change: the 3-barrier
// convergence-flag protocol is replaced by a single __syncthreads_or
// reduction (2 barriers/epoch instead of 4).
// Relaxation: monotone fl(w + exact-min8) on valid upper bounds => bit-exact
// float fixed point of the reference's 1024 Jacobi sweeps; zero-change epoch
// => fixed point verified. Backtrack: successor indices nxt[v] (exact OFFS
// first-occurrence argmin, source self-loop) composed in parallel into packed
// 3-hop words (n1 | n2<<10 | n3<<20); serial walk does one LDS per 3 path
// cells; sticky source self-loop keeps marks idempotent past the source,
// matching the reference's frozen-pos semantics.

#define BN 128
#define ST 35              // smem row stride (odd => conflict-free both axes)
#define INF_F 1000000000.0f
#define EPS_F 1e-6f
#define KP 2               // fwd+bwd sweep pairs per phase

__device__ __forceinline__ float shl(float v, int lane) {
    float t = __shfl_up_sync(0xffffffffu, v, 1);
    return (lane == 0) ? INF_F : t;
}
__device__ __forceinline__ float shr(float v, int lane) {
    float t = __shfl_down_sync(0xffffffffu, v, 1);
    return (lane == 31) ? INF_F : t;
}
__device__ __forceinline__ float min8f(float a, float b, float c, float d,
                                       float e, float f, float g, float h) {
    return fminf(fminf(fminf(a, b), fminf(c, d)),
                 fminf(fminf(e, f), fminf(g, h)));
}
// OFFS-order first-occurrence argmin; returns linear delta dr*32+dc.
// OFFS: (-1,-1)->-33, (-1,0)->-32, (-1,1)->-31, (0,-1)->-1, (0,1)->+1,
//       (1,-1)->+31,  (1,0)->+32,  (1,1)->+33
__device__ __forceinline__ int pick8d(float a0, float a1, float a2, float a3,
                                      float a4, float a5, float a6, float a7) {
    float bb = a0; int bd = -33;
    if (a1 < bb) { bb = a1; bd = -32; }
    if (a2 < bb) { bb = a2; bd = -31; }
    if (a3 < bb) { bb = a3; bd = -1; }
    if (a4 < bb) { bb = a4; bd = 1; }
    if (a5 < bb) { bb = a5; bd = 31; }
    if (a6 < bb) { bb = a6; bd = 32; }
    if (a7 < bb) { bb = a7; bd = 33; }
    return bd;
}

// One GS fwd+bwd sweep pair over 4 owned cells per lane (R4 version:
// fresh shfls per row, diagonal-inclusive Gauss-Seidel).
__device__ __forceinline__ void sweep_pair(volatile float* vd,
                                           const float w[4], float d[4],
                                           int i0, int di, int ix, int iy,
                                           int lane, bool& any)
{
    // forward sweep
    {
        float X = vd[ix], Y = vd[iy];
        float p = X, pl = shl(X, lane), pr = shr(X, lane);
        #pragma unroll
        for (int i = 0; i < 4; ++i) {
            float nx = (i < 3) ? d[i + 1] : Y;
            float nl = shl(nx, lane),  nr = shr(nx, lane);
            float cl = shl(d[i], lane), cr = shr(d[i], lane);
            float v = w[i] + min8f(pl, p, pr, cl, cr, nl, nx, nr);
            if (v < d[i]) { d[i] = v; vd[i0 + i * di] = v; any = true; }
            p = d[i]; pl = shl(p, lane); pr = shr(p, lane);
        }
    }
    // backward sweep
    {
        float X = vd[ix], Y = vd[iy];
        float p = Y, pl = shl(Y, lane), pr = shr(Y, lane);
        #pragma unroll
        for (int i = 3; i >= 0; --i) {
            float nx = (i > 0) ? d[i - 1] : X;
            float nl = shl(nx, lane),  nr = shr(nx, lane);
            float cl = shl(d[i], lane), cr = shr(d[i], lane);
            float v = w[i] + min8f(nl, nx, nr, cl, cr, pl, p, pr);
            if (v < d[i]) { d[i] = v; vd[i0 + i * di] = v; any = true; }
            p = d[i]; pl = shl(p, lane); pr = shr(p, lane);
        }
    }
}

__global__ void __launch_bounds__(256, 1)
bba_kernel(const float* __restrict__ weights,
           const int*   __restrict__ source,
           const int*   __restrict__ target,
           float*       __restrict__ out)
{
    __shared__ float dist[34 * ST];     // padded 34x34, stride 35
    __shared__ float wsh[32][33];       // weights, conflict-free both axes
    __shared__ int   nxt[1024];         // 1-hop successor indices
    __shared__ int   pk[1024];          // packed 3-hop words
    volatile float* vd = dist;

    const int b    = blockIdx.x;
    const int tid  = threadIdx.x;
    const int wpid = tid >> 5;          // warp id 0..7
    const int lane = tid & 31;
    const int r0   = 4 * wpid;          // V band first row
    const int c0   = 4 * wpid;          // H band first col

    // Zero poisoned output slice.
    #pragma unroll
    for (int i = 0; i < 4; ++i) out[b * 1024 + i * 256 + tid] = 0.0f;

    for (int i = tid; i < 34 * ST; i += 256) dist[i] = INF_F;

    // Weights (+EPS), V-layout load, stash in smem for H-layout reads.
    const float* wb = weights + b * 1024;
    float wv[4], wh[4];
    #pragma unroll
    for (int i = 0; i < 4; ++i) {
        wv[i] = wb[(r0 + i) * 32 + lane] + EPS_F;
        wsh[r0 + i][lane] = wv[i];
    }

    const int sr = source[2 * b + 0];
    const int sc = source[2 * b + 1];
    const int tr = target[2 * b + 0];
    const int tc = target[2 * b + 1];

    __syncthreads();

    #pragma unroll
    for (int i = 0; i < 4; ++i) wh[i] = wsh[lane][c0 + i];
    if (tid == 0) dist[(sr + 1) * ST + (sc + 1)] = wsh[sr][sc];
    __syncthreads();

    // Indices for both orientations.
    const int v_i0 = (r0 + 1) * ST + (lane + 1);   // own cells, step ST
    const int v_ix = (r0 + 0) * ST + (lane + 1);   // row above band
    const int v_iy = (r0 + 5) * ST + (lane + 1);   // row below band
    const int h_i0 = (lane + 1) * ST + (c0 + 1);   // own cells, step 1
    const int h_ix = (lane + 1) * ST + (c0 + 0);   // col left of band
    const int h_iy = (lane + 1) * ST + (c0 + 5);   // col right of band

    float d[4];

    for (;;) {
        bool any = false;

        // V phase
        #pragma unroll
        for (int i = 0; i < 4; ++i) d[i] = vd[v_i0 + i * ST];
        #pragma unroll 1
        for (int k = 0; k < KP; ++k)
            sweep_pair(vd, wv, d, v_i0, ST, v_ix, v_iy, lane, any);

        __syncthreads();                 // V writes visible to H phase

        // H phase
        #pragma unroll
        for (int i = 0; i < 4; ++i) d[i] = vd[h_i0 + i];
        #pragma unroll 1
        for (int k = 0; k < KP; ++k)
            sweep_pair(vd, wh, d, h_i0, 1, h_ix, h_iy, lane, any);

        if (!__syncthreads_or((int)any)) break;   // zero-change epoch => d*
    }

    const int sidx = (sr << 5) + sc;

    // 1-hop successors (V layout), OFFS order, source = self-loop:
    // (-1,-1),(-1,0),(-1,1),(0,-1),(0,1),(1,-1),(1,0),(1,1)
    {
        #pragma unroll
        for (int i = 0; i < 4; ++i) d[i] = vd[v_i0 + i * ST];
        float X  = vd[v_ix], Y = vd[v_iy];
        float XL = shl(X, lane),    XR = shr(X, lane);
        float L0 = shl(d[0], lane), R0 = shr(d[0], lane);
        float L1 = shl(d[1], lane), R1 = shr(d[1], lane);
        float L2 = shl(d[2], lane), R2 = shr(d[2], lane);
        float L3 = shl(d[3], lane), R3 = shr(d[3], lane);
        float YL = shl(Y, lane),    YR = shr(Y, lane);
        int dl[4];
        dl[0] = pick8d(XL, X,    XR, L0, R0, L1, d[1], R1);
        dl[1] = pick8d(L0, d[0], R0, L1, R1, L2, d[2], R2);
        dl[2] = pick8d(L1, d[1], R1, L2, R2, L3, d[3], R3);
        dl[3] = pick8d(L2, d[2], R2, L3, R3, YL, Y,    YR);
        #pragma unroll
        for (int i = 0; i < 4; ++i) {
            const int cell = ((r0 + i) << 5) + lane;
            nxt[cell] = (cell == sidx) ? sidx : (cell + dl[i]);
        }
    }
    __syncthreads();

    // Compose 3 hops into one packed word per cell (parallel).
    #pragma unroll
    for (int k = 0; k < 4; ++k) {
        const int v  = k * 256 + tid;
        const int n1 = nxt[v];
        const int n2 = nxt[n1];
        const int n3 = nxt[n2];
        pk[v] = n1 | (n2 << 10) | (n3 << 20);
    }
    __syncthreads();

    // Serial walk: one LDS per 3 path cells (sticky at source).
    if (tid == 0) {
        int idx = (tr << 5) + tc;
        float* o = out + b * 1024;
        for (int step = 0; step < 344; ++step) {
            const int w3 = pk[idx];
            o[idx] = 1.0f;
            if (idx == sidx) break;
            o[w3 & 1023] = 1.0f;           // n1 (source-sticky => idempotent)
            o[(w3 >> 10) & 1023] = 1.0f;   // n2
            idx = (w3 >> 20) & 1023;       // jump 3 hops
        }
    }
}

extern "C" void kernel_launch(void* const* d_in, const int* in_sizes, int n_in,
                              void* d_out, int out_size)
{
    const float* weights = (const float*)d_in[0];
    const int*   source  = (const int*)d_in[1];
    const int*   target  = (const int*)d_in[2];
    float*       out     = (float*)d_out;

    bba_kernel<<<BN, 256>>>(weights, source, target, out);
}